// round 9
// baseline (speedup 1.0000x reference)
#include <cuda_runtime.h>
#include <cstddef>

#define N_TOKENS 131072
#define TM 64
#define NTILES (N_TOKENS / TM)     // 2048
#define THREADS 512
#define GRID 148

// ---- shared memory layout (in floats) ----
#define WALL_SZ   (64 * 640)       // 163840 B
#define BUFA_STRIDE 68             // padded token stride
#define BUFA_SZ   (64 * BUFA_STRIDE)
#define WALL_OFF  0
#define BUFA_OFF  (WALL_OFF + WALL_SZ)        // kv_t -> x_t -> h2_t (reused)
#define H1_OFF    (BUFA_OFF + BUFA_SZ)        // h1_t + epilogue partials
#define D1_OFF    (H1_OFF + BUFA_SZ)
#define D2_OFF    (D1_OFF + 64 * 64)
#define D3_OFF    (D2_OFF + 64 * 32)
#define SMEM_FLOATS (D3_OFF + 32 * 64)
#define SMEM_BYTES (SMEM_FLOATS * 4)          // 231424 B

// epilogue partial arrays inside sH1 (dead between MLP2-read and MLP1-write)
#define PS_SS 0        // [64 tok][4 blk] sum of att^2
#define PS_MX 256      // [64 tok][4 blk] max of v*scale
#define PS_ES 512      // [64 tok][4 blk] exp-sum

typedef unsigned long long u64;

__device__ __forceinline__ u64 pack2(float lo, float hi) {
    u64 r; asm("mov.b64 %0, {%1, %2};" : "=l"(r) : "f"(lo), "f"(hi)); return r;
}
__device__ __forceinline__ void unpack2(u64 v, float& lo, float& hi) {
    asm("mov.b64 {%0, %1}, %2;" : "=f"(lo), "=f"(hi) : "l"(v));
}
__device__ __forceinline__ u64 ffma2(u64 a, u64 b, u64 c) {
    u64 d; asm("fma.rn.f32x2 %0, %1, %2, %3;" : "=l"(d) : "l"(a), "l"(b), "l"(c)); return d;
}

// Packed weight matrix Wall[64 j][640 c], built per-launch by prep kernel.
// c in [0,64): key_W ; [64,128): value_W ; [128,576): T_W (p-major, i minor) ; [576,640): T_b
__device__ float g_Wall[64 * 640];

__global__ void prep_kernel(const float* __restrict__ keyW, const float* __restrict__ valW,
                            const float* __restrict__ TW,   const float* __restrict__ Tb) {
    int idx = blockIdx.x * blockDim.x + threadIdx.x;
    if (idx >= 64 * 640) return;
    int j = idx / 640;
    int c = idx % 640;
    float w;
    if (c < 64)       w = keyW[j * 64 + c];
    else if (c < 128) w = valW[j * 64 + (c - 64)];
    else if (c < 576) { int p = (c - 128) >> 6; int i = c & 63; w = TW[p * 4096 + i * 64 + j]; }
    else              { int i = c - 576;                        w = Tb[i * 64 + j]; }
    g_Wall[idx] = w;
}

__global__ void __launch_bounds__(THREADS, 1)
fused_kernel(const float* __restrict__ kv_in, const float* __restrict__ query,
             const float* __restrict__ key_b, const float* __restrict__ value_b,
             const float* __restrict__ d1W, const float* __restrict__ d1b,
             const float* __restrict__ d2W, const float* __restrict__ d2b,
             const float* __restrict__ d3W, const float* __restrict__ d3b,
             const float* __restrict__ scale_p, float* __restrict__ out)
{
    extern __shared__ float sm[];
    float* sWall = sm + WALL_OFF;
    float* sA    = sm + BUFA_OFF;
    float* sH1   = sm + H1_OFF;
    float* sD1   = sm + D1_OFF;
    float* sD2   = sm + D2_OFF;
    float* sD3   = sm + D3_OFF;

    const int tid  = threadIdx.x;
    const int lane = tid & 31;
    const int warp = tid >> 5;
    const int ct   = lane & 3;                 // col-group within warp (0..3)
    const int tt   = lane >> 2;                // token-group within warp (0..7)
    const int blk  = warp & 3;                 // column block of this warp
    const int cg   = blk * 4 + ct;             // global col-group: cols [4cg, 4cg+4)
    const int tg   = (warp >> 2) * 8 + tt;     // global token-group: tokens {2tg, 2tg+1}
    const int c0   = 4 * cg;

    // ---- one-time weight staging into smem ----
    for (int i = tid; i < 64 * 640; i += THREADS) sWall[i] = g_Wall[i];
    for (int i = tid; i < 64 * 64;  i += THREADS) sD1[i] = d1W[i];
    for (int i = tid; i < 64 * 32;  i += THREADS) sD2[i] = d2W[i];
    for (int i = tid; i < 32 * 64;  i += THREADS) sD3[i] = d3W[i];

    const float scale = __ldg(scale_p);

    for (int tile = blockIdx.x; tile < NTILES; tile += gridDim.x) {
        const int base = tile * TM;

        __syncthreads();   // sA free from previous tile's MLP3 reads
        // ---- load kv tile transposed: sA[j][tok] ----
#pragma unroll
        for (int r = 0; r < 2; r++) {
            int q4 = tid + r * THREADS;           // 0..1023 float4 chunks
            int t  = q4 >> 4;                     // token 0..63
            int j4 = (q4 & 15) << 2;              // channel group
            float4 d = *reinterpret_cast<const float4*>(kv_in + (size_t)(base + t) * 64 + j4);
            sA[(j4 + 0) * BUFA_STRIDE + t] = d.x;
            sA[(j4 + 1) * BUFA_STRIDE + t] = d.y;
            sA[(j4 + 2) * BUFA_STRIDE + t] = d.z;
            sA[(j4 + 3) * BUFA_STRIDE + t] = d.w;
        }

        // query coefficients for this thread's 2 tokens, broadcast-packed (loop-invariant)
        u64 qp2[2][7];
#pragma unroll
        for (int t = 0; t < 2; t++)
#pragma unroll
            for (int p = 0; p < 7; p++) {
                float q = __ldg(query + (size_t)(base + 2 * tg + t) * 7 + p);
                qp2[t][p] = pack2(q, q);
            }
        __syncthreads();

        // ---- fused GEMM: k, v, and on-the-fly folded hypernetwork q ----
        // thread: 2 tokens x 4 cols, accumulators packed f32x2 over cols.
        u64 xk[2][2], xv[2][2], xx[2][2];
#pragma unroll
        for (int t = 0; t < 2; t++) {
            xk[t][0] = 0; xk[t][1] = 0;
            xv[t][0] = 0; xv[t][1] = 0;
            xx[t][0] = 0; xx[t][1] = 0;
        }

#pragma unroll 4
        for (int j = 0; j < 64; j++) {
            float2 av = *reinterpret_cast<const float2*>(sA + j * BUFA_STRIDE + 2 * tg);
            u64 a2t[2] = { pack2(av.x, av.x), pack2(av.y, av.y) };
            const float* wrow = sWall + j * 640 + c0;
            ulonglong2 bk  = *reinterpret_cast<const ulonglong2*>(wrow);
            ulonglong2 bvv = *reinterpret_cast<const ulonglong2*>(wrow + 64);
            ulonglong2 bu0 = *reinterpret_cast<const ulonglong2*>(wrow + 2 * 64);
            ulonglong2 bu1 = *reinterpret_cast<const ulonglong2*>(wrow + 3 * 64);
            ulonglong2 bu2 = *reinterpret_cast<const ulonglong2*>(wrow + 4 * 64);
            ulonglong2 bu3 = *reinterpret_cast<const ulonglong2*>(wrow + 5 * 64);
            ulonglong2 bu4 = *reinterpret_cast<const ulonglong2*>(wrow + 6 * 64);
            ulonglong2 bu5 = *reinterpret_cast<const ulonglong2*>(wrow + 7 * 64);
            ulonglong2 bu6 = *reinterpret_cast<const ulonglong2*>(wrow + 8 * 64);
            ulonglong2 bb  = *reinterpret_cast<const ulonglong2*>(wrow + 9 * 64);
#pragma unroll
            for (int t = 0; t < 2; t++) {
                u64 a2 = a2t[t];
                xk[t][0] = ffma2(a2, bk.x,  xk[t][0]);
                xk[t][1] = ffma2(a2, bk.y,  xk[t][1]);
                xv[t][0] = ffma2(a2, bvv.x, xv[t][0]);
                xv[t][1] = ffma2(a2, bvv.y, xv[t][1]);
                u64 w0 = bb.x, w1 = bb.y;
                w0 = ffma2(qp2[t][0], bu0.x, w0); w1 = ffma2(qp2[t][0], bu0.y, w1);
                w0 = ffma2(qp2[t][1], bu1.x, w0); w1 = ffma2(qp2[t][1], bu1.y, w1);
                w0 = ffma2(qp2[t][2], bu2.x, w0); w1 = ffma2(qp2[t][2], bu2.y, w1);
                w0 = ffma2(qp2[t][3], bu3.x, w0); w1 = ffma2(qp2[t][3], bu3.y, w1);
                w0 = ffma2(qp2[t][4], bu4.x, w0); w1 = ffma2(qp2[t][4], bu4.y, w1);
                w0 = ffma2(qp2[t][5], bu5.x, w0); w1 = ffma2(qp2[t][5], bu5.y, w1);
                w0 = ffma2(qp2[t][6], bu6.x, w0); w1 = ffma2(qp2[t][6], bu6.y, w1);
                xx[t][0] = ffma2(a2, w0, xx[t][0]);
                xx[t][1] = ffma2(a2, w1, xx[t][1]);
            }
        }

        // ---- epilogue stage 1: local att/sv, in-warp (4-lane) partials ----
        float kb[4], vb[4];
#pragma unroll
        for (int i = 0; i < 4; i++) {
            kb[i] = __ldg(key_b   + c0 + i);
            vb[i] = __ldg(value_b + c0 + i);
        }
        float att[2][4], sv[2][4], inv_n[2];
        float ssl[2], mxl[2];
#pragma unroll
        for (int t = 0; t < 2; t++) {
            float q_[4], k_[4], v_[4];
            unpack2(xx[t][0], q_[0], q_[1]); unpack2(xx[t][1], q_[2], q_[3]);
            unpack2(xk[t][0], k_[0], k_[1]); unpack2(xk[t][1], k_[2], k_[3]);
            unpack2(xv[t][0], v_[0], v_[1]); unpack2(xv[t][1], v_[2], v_[3]);
            float ss = 0.f, mx = -1e30f;
#pragma unroll
            for (int i = 0; i < 4; i++) {
                att[t][i] = q_[i] * (k_[i] + kb[i]);
                ss += att[t][i] * att[t][i];
                sv[t][i] = (v_[i] + vb[i]) * scale;
                mx = fmaxf(mx, sv[t][i]);
            }
            ss += __shfl_xor_sync(0xffffffffu, ss, 1);
            ss += __shfl_xor_sync(0xffffffffu, ss, 2);
            mx = fmaxf(mx, __shfl_xor_sync(0xffffffffu, mx, 1));
            mx = fmaxf(mx, __shfl_xor_sync(0xffffffffu, mx, 2));
            ssl[t] = ss; mxl[t] = mx;
        }
        if (ct == 0) {
#pragma unroll
            for (int t = 0; t < 2; t++) {
                int tok = 2 * tg + t;
                sH1[PS_SS + tok * 4 + blk] = ssl[t];
                sH1[PS_MX + tok * 4 + blk] = mxl[t];
            }
        }
        __syncthreads();

        // ---- stage 2: totals for norm/max, local exp-sum partials ----
        float esl[2];
#pragma unroll
        for (int t = 0; t < 2; t++) {
            int tok = 2 * tg + t;
            float4 s4 = *reinterpret_cast<const float4*>(sH1 + PS_SS + tok * 4);
            float ss_tot = (s4.x + s4.y) + (s4.z + s4.w);
            inv_n[t] = 1.0f / fmaxf(sqrtf(ss_tot), 1e-8f);
            float4 m4 = *reinterpret_cast<const float4*>(sH1 + PS_MX + tok * 4);
            float mx = fmaxf(fmaxf(m4.x, m4.y), fmaxf(m4.z, m4.w));
            float es = 0.f;
#pragma unroll
            for (int i = 0; i < 4; i++) {
                sv[t][i] = __expf(sv[t][i] - mx);
                es += sv[t][i];
            }
            es += __shfl_xor_sync(0xffffffffu, es, 1);
            es += __shfl_xor_sync(0xffffffffu, es, 2);
            esl[t] = es;
        }
        if (ct == 0) {
#pragma unroll
            for (int t = 0; t < 2; t++)
                sH1[PS_ES + (2 * tg + t) * 4 + blk] = esl[t];
        }
        __syncthreads();

        // ---- stage 3: finish x, write x_t into sA ----
        {
            float x[2][4];
#pragma unroll
            for (int t = 0; t < 2; t++) {
                float4 e4 = *reinterpret_cast<const float4*>(sH1 + PS_ES + (2 * tg + t) * 4);
                float inv_e = 1.0f / ((e4.x + e4.y) + (e4.z + e4.w));
#pragma unroll
                for (int i = 0; i < 4; i++)
                    x[t][i] = (att[t][i] * inv_n[t]) * (sv[t][i] * inv_e);
            }
#pragma unroll
            for (int i = 0; i < 4; i++)
                *reinterpret_cast<float2*>(sA + (c0 + i) * BUFA_STRIDE + 2 * tg) =
                    make_float2(x[0][i], x[1][i]);
        }
        __syncthreads();

        // ---- MLP1: h1 = relu(x @ d1 + b1) ----
        u64 b1p0 = pack2(__ldg(d1b + c0),     __ldg(d1b + c0 + 1));
        u64 b1p1 = pack2(__ldg(d1b + c0 + 2), __ldg(d1b + c0 + 3));
        u64 h1a[2][2] = { { b1p0, b1p1 }, { b1p0, b1p1 } };
#pragma unroll 8
        for (int j = 0; j < 64; j++) {
            float2 av = *reinterpret_cast<const float2*>(sA + j * BUFA_STRIDE + 2 * tg);
            u64 a0 = pack2(av.x, av.x), a1 = pack2(av.y, av.y);
            ulonglong2 bw = *reinterpret_cast<const ulonglong2*>(sD1 + j * 64 + c0);
            h1a[0][0] = ffma2(a0, bw.x, h1a[0][0]);
            h1a[0][1] = ffma2(a0, bw.y, h1a[0][1]);
            h1a[1][0] = ffma2(a1, bw.x, h1a[1][0]);
            h1a[1][1] = ffma2(a1, bw.y, h1a[1][1]);
        }
#pragma unroll
        for (int p = 0; p < 2; p++) {
            float x00, x01, x10, x11;
            unpack2(h1a[0][p], x00, x01);
            unpack2(h1a[1][p], x10, x11);
            *reinterpret_cast<float2*>(sH1 + (c0 + 2 * p)     * BUFA_STRIDE + 2 * tg) =
                make_float2(fmaxf(x00, 0.f), fmaxf(x10, 0.f));
            *reinterpret_cast<float2*>(sH1 + (c0 + 2 * p + 1) * BUFA_STRIDE + 2 * tg) =
                make_float2(fmaxf(x01, 0.f), fmaxf(x11, 0.f));
        }
        __syncthreads();

        // ---- MLP2: h2 = relu(h1 @ d2 + b2), cols {2cg, 2cg+1} ----
        u64 b2p = pack2(__ldg(d2b + 2 * cg), __ldg(d2b + 2 * cg + 1));
        u64 h2a[2] = { b2p, b2p };
#pragma unroll 8
        for (int j = 0; j < 64; j++) {
            float2 av = *reinterpret_cast<const float2*>(sH1 + j * BUFA_STRIDE + 2 * tg);
            u64 bw = *reinterpret_cast<const u64*>(sD2 + j * 32 + 2 * cg);
            h2a[0] = ffma2(pack2(av.x, av.x), bw, h2a[0]);
            h2a[1] = ffma2(pack2(av.y, av.y), bw, h2a[1]);
        }
        {
            float y00, y01, y10, y11;
            unpack2(h2a[0], y00, y01);
            unpack2(h2a[1], y10, y11);
            *reinterpret_cast<float2*>(sA + (2 * cg)     * BUFA_STRIDE + 2 * tg) =
                make_float2(fmaxf(y00, 0.f), fmaxf(y10, 0.f));
            *reinterpret_cast<float2*>(sA + (2 * cg + 1) * BUFA_STRIDE + 2 * tg) =
                make_float2(fmaxf(y01, 0.f), fmaxf(y11, 0.f));
        }
        __syncthreads();

        // ---- MLP3: out = h2 @ d3 + b3 ----
        u64 b3p0 = pack2(__ldg(d3b + c0),     __ldg(d3b + c0 + 1));
        u64 b3p1 = pack2(__ldg(d3b + c0 + 2), __ldg(d3b + c0 + 3));
        u64 oa[2][2] = { { b3p0, b3p1 }, { b3p0, b3p1 } };
#pragma unroll 8
        for (int j = 0; j < 32; j++) {
            float2 av = *reinterpret_cast<const float2*>(sA + j * BUFA_STRIDE + 2 * tg);
            u64 a0 = pack2(av.x, av.x), a1 = pack2(av.y, av.y);
            ulonglong2 bw = *reinterpret_cast<const ulonglong2*>(sD3 + j * 64 + c0);
            oa[0][0] = ffma2(a0, bw.x, oa[0][0]);
            oa[0][1] = ffma2(a0, bw.y, oa[0][1]);
            oa[1][0] = ffma2(a1, bw.x, oa[1][0]);
            oa[1][1] = ffma2(a1, bw.y, oa[1][1]);
        }
#pragma unroll
        for (int t = 0; t < 2; t++) {
            float o0, o1, o2, o3;
            unpack2(oa[t][0], o0, o1);
            unpack2(oa[t][1], o2, o3);
            *reinterpret_cast<float4*>(out + (size_t)(base + 2 * tg + t) * 64 + c0) =
                make_float4(o0, o1, o2, o3);
        }
    }
}

extern "C" void kernel_launch(void* const* d_in, const int* in_sizes, int n_in,
                              void* d_out, int out_size) {
    const float* kv      = (const float*)d_in[0];
    const float* query   = (const float*)d_in[1];
    const float* keyW    = (const float*)d_in[2];
    const float* keyb    = (const float*)d_in[3];
    const float* valW    = (const float*)d_in[4];
    const float* valb    = (const float*)d_in[5];
    const float* TW      = (const float*)d_in[6];
    const float* Tb      = (const float*)d_in[7];
    const float* d1W     = (const float*)d_in[8];
    const float* d1b     = (const float*)d_in[9];
    const float* d2W     = (const float*)d_in[10];
    const float* d2b     = (const float*)d_in[11];
    const float* d3W     = (const float*)d_in[12];
    const float* d3b     = (const float*)d_in[13];
    const float* scale   = (const float*)d_in[14];
    float* out           = (float*)d_out;

    cudaFuncSetAttribute(fused_kernel, cudaFuncAttributeMaxDynamicSharedMemorySize, SMEM_BYTES);

    prep_kernel<<<160, 256>>>(keyW, valW, TW, Tb);
    fused_kernel<<<GRID, THREADS, SMEM_BYTES>>>(kv, query, keyb, valb,
                                                d1W, d1b, d2W, d2b, d3W, d3b,
                                                scale, out);
}

// round 10
// speedup vs baseline: 1.4180x; 1.4180x over previous
#include <cuda_runtime.h>
#include <cstddef>

#define N_TOKENS 131072
#define TM 64
#define NTILES (N_TOKENS / TM)     // 2048
#define THREADS 256
#define GRID 148

// ---- shared memory layout (in floats) ----
#define WALL_SZ   (64 * 640)       // 163840 B
#define BUFA_STRIDE 68             // padded token stride (16B-aligned float4)
#define BUFA_SZ   (64 * BUFA_STRIDE)
#define WALL_OFF  0
#define BUFA_OFF  (WALL_OFF + WALL_SZ)        // kv_t -> x_t -> h2_t (reused)
#define H1_OFF    (BUFA_OFF + BUFA_SZ)        // h1_t
#define D1_OFF    (H1_OFF + BUFA_SZ)
#define D2_OFF    (D1_OFF + 64 * 64)
#define D3_OFF    (D2_OFF + 64 * 32)
#define SMEM_FLOATS (D3_OFF + 32 * 64)
#define SMEM_BYTES (SMEM_FLOATS * 4)          // 231424 B (< 232448 opt-in limit)

typedef unsigned long long u64;

__device__ __forceinline__ u64 pack2(float lo, float hi) {
    u64 r; asm("mov.b64 %0, {%1, %2};" : "=l"(r) : "f"(lo), "f"(hi)); return r;
}
__device__ __forceinline__ void unpack2(u64 v, float& lo, float& hi) {
    asm("mov.b64 {%0, %1}, %2;" : "=f"(lo), "=f"(hi) : "l"(v));
}
__device__ __forceinline__ u64 ffma2(u64 a, u64 b, u64 c) {
    u64 d; asm("fma.rn.f32x2 %0, %1, %2, %3;" : "=l"(d) : "l"(a), "l"(b), "l"(c)); return d;
}

// Packed weight matrix Wall[64 j][640 c], built per-launch by prep kernel.
// c in [0,64): key_W ; [64,128): value_W ; [128,576): T_W (p-major, i minor) ; [576,640): T_b
__device__ float g_Wall[64 * 640];

__global__ void prep_kernel(const float* __restrict__ keyW, const float* __restrict__ valW,
                            const float* __restrict__ TW,   const float* __restrict__ Tb) {
    int idx = blockIdx.x * blockDim.x + threadIdx.x;
    if (idx >= 64 * 640) return;
    int j = idx / 640;
    int c = idx % 640;
    float w;
    if (c < 64)       w = keyW[j * 64 + c];
    else if (c < 128) w = valW[j * 64 + (c - 64)];
    else if (c < 576) { int p = (c - 128) >> 6; int i = c & 63; w = TW[p * 4096 + i * 64 + j]; }
    else              { int i = c - 576;                        w = Tb[i * 64 + j]; }
    g_Wall[idx] = w;
}

__global__ void __launch_bounds__(THREADS, 1)
fused_kernel(const float* __restrict__ kv_in, const float* __restrict__ query,
             const float* __restrict__ key_b, const float* __restrict__ value_b,
             const float* __restrict__ d1W, const float* __restrict__ d1b,
             const float* __restrict__ d2W, const float* __restrict__ d2b,
             const float* __restrict__ d3W, const float* __restrict__ d3b,
             const float* __restrict__ scale_p, float* __restrict__ out)
{
    extern __shared__ float sm[];
    float* sWall = sm + WALL_OFF;
    float* sA    = sm + BUFA_OFF;
    float* sH1   = sm + H1_OFF;
    float* sD1   = sm + D1_OFF;
    float* sD2   = sm + D2_OFF;
    float* sD3   = sm + D3_OFF;

    const int tid = threadIdx.x;
    const int ct  = tid & 15;    // column-group thread (16): 4 cols each
    const int tt  = tid >> 4;    // token-group thread (16): 4 contiguous tokens each

    // ---- one-time weight staging into smem ----
    for (int i = tid; i < 64 * 640; i += THREADS) sWall[i] = g_Wall[i];
    for (int i = tid; i < 64 * 64;  i += THREADS) sD1[i] = d1W[i];
    for (int i = tid; i < 64 * 32;  i += THREADS) sD2[i] = d2W[i];
    for (int i = tid; i < 32 * 64;  i += THREADS) sD3[i] = d3W[i];

    const float scale = __ldg(scale_p);
    float kb[4], vb[4], b3v[4];
#pragma unroll
    for (int i = 0; i < 4; i++) {
        kb[i]  = __ldg(key_b   + 4 * ct + i);
        vb[i]  = __ldg(value_b + 4 * ct + i);
        b3v[i] = __ldg(d3b     + 4 * ct + i);
    }
    u64 b1p0 = pack2(__ldg(d1b + 4 * ct), __ldg(d1b + 4 * ct + 1));
    u64 b1p1 = pack2(__ldg(d1b + 4 * ct + 2), __ldg(d1b + 4 * ct + 3));
    u64 b2p  = pack2(__ldg(d2b + 2 * ct), __ldg(d2b + 2 * ct + 1));
    u64 b3p0 = pack2(b3v[0], b3v[1]);
    u64 b3p1 = pack2(b3v[2], b3v[3]);

    const int tile0 = blockIdx.x;

    // ---- prologue prefetch: tile0's kv + query into registers ----
    float4 pk[4];   // kv chunks (transposed-store pattern)
    float4 pq7[7];  // this thread's 4 tokens x 7 query coeffs (contiguous 28 floats)
    {
        const int base = tile0 * TM;
#pragma unroll
        for (int r = 0; r < 4; r++) {
            int q4 = tid + r * THREADS;
            int t  = q4 >> 4;
            int j4 = (q4 & 15) << 2;
            pk[r] = *reinterpret_cast<const float4*>(kv_in + (size_t)(base + t) * 64 + j4);
        }
        const float* qp = query + (size_t)(base + 4 * tt) * 7;
#pragma unroll
        for (int r = 0; r < 7; r++)
            pq7[r] = *reinterpret_cast<const float4*>(qp + 4 * r);
    }

    for (int tile = tile0; tile < NTILES; tile += GRID) {
        const int base = tile * TM;

        __syncthreads();   // sA free (prev tile's MLP3 reads done; 1st iter: staging done)
        // ---- commit prefetched kv tile transposed: sA[j][tok] ----
#pragma unroll
        for (int r = 0; r < 4; r++) {
            int q4 = tid + r * THREADS;
            int t  = q4 >> 4;
            int j4 = (q4 & 15) << 2;
            sA[(j4 + 0) * BUFA_STRIDE + t] = pk[r].x;
            sA[(j4 + 1) * BUFA_STRIDE + t] = pk[r].y;
            sA[(j4 + 2) * BUFA_STRIDE + t] = pk[r].z;
            sA[(j4 + 3) * BUFA_STRIDE + t] = pk[r].w;
        }
        // unpack query coeffs -> broadcast-packed qp2[tok][p]
        float qf[28];
#pragma unroll
        for (int r = 0; r < 7; r++) {
            qf[4 * r + 0] = pq7[r].x; qf[4 * r + 1] = pq7[r].y;
            qf[4 * r + 2] = pq7[r].z; qf[4 * r + 3] = pq7[r].w;
        }
        u64 qp2[4][7];
#pragma unroll
        for (int t = 0; t < 4; t++)
#pragma unroll
            for (int p = 0; p < 7; p++) {
                float q = qf[t * 7 + p];
                qp2[t][p] = pack2(q, q);
            }
        __syncthreads();

        // ---- fused GEMM: k, v, and on-the-fly folded hypernetwork q ----
        u64 xk[4][2], xv[4][2], xx[4][2];
#pragma unroll
        for (int t = 0; t < 4; t++) {
            xk[t][0] = 0; xk[t][1] = 0;
            xv[t][0] = 0; xv[t][1] = 0;
            xx[t][0] = 0; xx[t][1] = 0;
        }

#pragma unroll 4
        for (int j = 0; j < 64; j++) {
            float4 av = *reinterpret_cast<const float4*>(sA + j * BUFA_STRIDE + 4 * tt);
            float a_[4] = {av.x, av.y, av.z, av.w};
            const float* wrow = sWall + j * 640 + 4 * ct;
            ulonglong2 bk  = *reinterpret_cast<const ulonglong2*>(wrow);
            ulonglong2 bvv = *reinterpret_cast<const ulonglong2*>(wrow + 64);
            ulonglong2 bu0 = *reinterpret_cast<const ulonglong2*>(wrow + 2 * 64);
            ulonglong2 bu1 = *reinterpret_cast<const ulonglong2*>(wrow + 3 * 64);
            ulonglong2 bu2 = *reinterpret_cast<const ulonglong2*>(wrow + 4 * 64);
            ulonglong2 bu3 = *reinterpret_cast<const ulonglong2*>(wrow + 5 * 64);
            ulonglong2 bu4 = *reinterpret_cast<const ulonglong2*>(wrow + 6 * 64);
            ulonglong2 bu5 = *reinterpret_cast<const ulonglong2*>(wrow + 7 * 64);
            ulonglong2 bu6 = *reinterpret_cast<const ulonglong2*>(wrow + 8 * 64);
            ulonglong2 bb  = *reinterpret_cast<const ulonglong2*>(wrow + 9 * 64);
#pragma unroll
            for (int t = 0; t < 4; t++) {
                u64 a2 = pack2(a_[t], a_[t]);
                xk[t][0] = ffma2(a2, bk.x,  xk[t][0]);
                xk[t][1] = ffma2(a2, bk.y,  xk[t][1]);
                xv[t][0] = ffma2(a2, bvv.x, xv[t][0]);
                xv[t][1] = ffma2(a2, bvv.y, xv[t][1]);
                u64 w0 = bb.x, w1 = bb.y;
                w0 = ffma2(qp2[t][0], bu0.x, w0); w1 = ffma2(qp2[t][0], bu0.y, w1);
                w0 = ffma2(qp2[t][1], bu1.x, w0); w1 = ffma2(qp2[t][1], bu1.y, w1);
                w0 = ffma2(qp2[t][2], bu2.x, w0); w1 = ffma2(qp2[t][2], bu2.y, w1);
                w0 = ffma2(qp2[t][3], bu3.x, w0); w1 = ffma2(qp2[t][3], bu3.y, w1);
                w0 = ffma2(qp2[t][4], bu4.x, w0); w1 = ffma2(qp2[t][4], bu4.y, w1);
                w0 = ffma2(qp2[t][5], bu5.x, w0); w1 = ffma2(qp2[t][5], bu5.y, w1);
                w0 = ffma2(qp2[t][6], bu6.x, w0); w1 = ffma2(qp2[t][6], bu6.y, w1);
                xx[t][0] = ffma2(a2, w0, xx[t][0]);
                xx[t][1] = ffma2(a2, w1, xx[t][1]);
            }
        }

        // ---- epilogue per token: normalize(q*k) * softmax(v*scale), 16-lane shfl ----
        float x[4][4];
#pragma unroll
        for (int t = 0; t < 4; t++) {
            float qv[4], kk[4], vv[4];
            unpack2(xx[t][0], qv[0], qv[1]); unpack2(xx[t][1], qv[2], qv[3]);
            unpack2(xk[t][0], kk[0], kk[1]); unpack2(xk[t][1], kk[2], kk[3]);
            unpack2(xv[t][0], vv[0], vv[1]); unpack2(xv[t][1], vv[2], vv[3]);

            float att[4], sv[4];
            float ss = 0.f;
#pragma unroll
            for (int i = 0; i < 4; i++) {
                att[i] = qv[i] * (kk[i] + kb[i]);
                ss += att[i] * att[i];
            }
            ss += __shfl_xor_sync(0xffffffffu, ss, 1);
            ss += __shfl_xor_sync(0xffffffffu, ss, 2);
            ss += __shfl_xor_sync(0xffffffffu, ss, 4);
            ss += __shfl_xor_sync(0xffffffffu, ss, 8);
            float inv_n = 1.0f / fmaxf(sqrtf(ss), 1e-8f);

            float mx = -1e30f;
#pragma unroll
            for (int i = 0; i < 4; i++) {
                sv[i] = (vv[i] + vb[i]) * scale;
                mx = fmaxf(mx, sv[i]);
            }
            mx = fmaxf(mx, __shfl_xor_sync(0xffffffffu, mx, 1));
            mx = fmaxf(mx, __shfl_xor_sync(0xffffffffu, mx, 2));
            mx = fmaxf(mx, __shfl_xor_sync(0xffffffffu, mx, 4));
            mx = fmaxf(mx, __shfl_xor_sync(0xffffffffu, mx, 8));

            float es = 0.f;
#pragma unroll
            for (int i = 0; i < 4; i++) {
                sv[i] = __expf(sv[i] - mx);
                es += sv[i];
            }
            es += __shfl_xor_sync(0xffffffffu, es, 1);
            es += __shfl_xor_sync(0xffffffffu, es, 2);
            es += __shfl_xor_sync(0xffffffffu, es, 4);
            es += __shfl_xor_sync(0xffffffffu, es, 8);
            float inv_e = 1.0f / es;

#pragma unroll
            for (int i = 0; i < 4; i++)
                x[t][i] = (att[i] * inv_n) * (sv[i] * inv_e);
        }

        __syncthreads();   // all GEMM reads of kv_t done -> reuse sA for x_t
#pragma unroll
        for (int i = 0; i < 4; i++) {
            *reinterpret_cast<float4*>(sA + (4 * ct + i) * BUFA_STRIDE + 4 * tt) =
                make_float4(x[0][i], x[1][i], x[2][i], x[3][i]);
        }
        __syncthreads();

        // ---- issue NEXT tile's prefetch (latency hidden behind MLP phases) ----
        {
            int nt = tile + GRID;
            int pbase = (nt < NTILES ? nt : tile0) * TM;   // deterministic in-bounds clamp
#pragma unroll
            for (int r = 0; r < 4; r++) {
                int q4 = tid + r * THREADS;
                int t  = q4 >> 4;
                int j4 = (q4 & 15) << 2;
                pk[r] = *reinterpret_cast<const float4*>(kv_in + (size_t)(pbase + t) * 64 + j4);
            }
            const float* qp = query + (size_t)(pbase + 4 * tt) * 7;
#pragma unroll
            for (int r = 0; r < 7; r++)
                pq7[r] = *reinterpret_cast<const float4*>(qp + 4 * r);
        }

        // ---- MLP1: h1 = relu(x @ d1 + b1) ----
        u64 h1p[4][2];
#pragma unroll
        for (int t = 0; t < 4; t++) { h1p[t][0] = b1p0; h1p[t][1] = b1p1; }
#pragma unroll 4
        for (int j = 0; j < 64; j++) {
            float4 av = *reinterpret_cast<const float4*>(sA + j * BUFA_STRIDE + 4 * tt);
            float a_[4] = {av.x, av.y, av.z, av.w};
            ulonglong2 bw = *reinterpret_cast<const ulonglong2*>(sD1 + j * 64 + 4 * ct);
#pragma unroll
            for (int t = 0; t < 4; t++) {
                u64 a2 = pack2(a_[t], a_[t]);
                h1p[t][0] = ffma2(a2, bw.x, h1p[t][0]);
                h1p[t][1] = ffma2(a2, bw.y, h1p[t][1]);
            }
        }
        {
            float h[4][4];
#pragma unroll
            for (int t = 0; t < 4; t++) {
                unpack2(h1p[t][0], h[t][0], h[t][1]);
                unpack2(h1p[t][1], h[t][2], h[t][3]);
            }
#pragma unroll
            for (int i = 0; i < 4; i++) {
                *reinterpret_cast<float4*>(sH1 + (4 * ct + i) * BUFA_STRIDE + 4 * tt) =
                    make_float4(fmaxf(h[0][i], 0.f), fmaxf(h[1][i], 0.f),
                                fmaxf(h[2][i], 0.f), fmaxf(h[3][i], 0.f));
            }
        }
        __syncthreads();

        // ---- MLP2: h2 = relu(h1 @ d2 + b2), 32 outputs -> 2 per ct-thread ----
        u64 g2p[4];
#pragma unroll
        for (int t = 0; t < 4; t++) g2p[t] = b2p;
#pragma unroll 4
        for (int j = 0; j < 64; j++) {
            float4 av = *reinterpret_cast<const float4*>(sH1 + j * BUFA_STRIDE + 4 * tt);
            float a_[4] = {av.x, av.y, av.z, av.w};
            u64 bw = *reinterpret_cast<const u64*>(sD2 + j * 32 + 2 * ct);
#pragma unroll
            for (int t = 0; t < 4; t++)
                g2p[t] = ffma2(pack2(a_[t], a_[t]), bw, g2p[t]);
        }
        {
            float g[4][2];
#pragma unroll
            for (int t = 0; t < 4; t++) unpack2(g2p[t], g[t][0], g[t][1]);
#pragma unroll
            for (int o = 0; o < 2; o++) {
                *reinterpret_cast<float4*>(sA + (2 * ct + o) * BUFA_STRIDE + 4 * tt) =
                    make_float4(fmaxf(g[0][o], 0.f), fmaxf(g[1][o], 0.f),
                                fmaxf(g[2][o], 0.f), fmaxf(g[3][o], 0.f));
            }
        }
        __syncthreads();

        // ---- MLP3: out = h2 @ d3 + b3 ----
        u64 o2[4][2];
#pragma unroll
        for (int t = 0; t < 4; t++) { o2[t][0] = b3p0; o2[t][1] = b3p1; }
#pragma unroll 4
        for (int j = 0; j < 32; j++) {
            float4 av = *reinterpret_cast<const float4*>(sA + j * BUFA_STRIDE + 4 * tt);
            float a_[4] = {av.x, av.y, av.z, av.w};
            ulonglong2 bw = *reinterpret_cast<const ulonglong2*>(sD3 + j * 64 + 4 * ct);
#pragma unroll
            for (int t = 0; t < 4; t++) {
                u64 a2 = pack2(a_[t], a_[t]);
                o2[t][0] = ffma2(a2, bw.x, o2[t][0]);
                o2[t][1] = ffma2(a2, bw.y, o2[t][1]);
            }
        }
#pragma unroll
        for (int t = 0; t < 4; t++) {
            float o_[4];
            unpack2(o2[t][0], o_[0], o_[1]);
            unpack2(o2[t][1], o_[2], o_[3]);
            *reinterpret_cast<float4*>(out + (size_t)(base + 4 * tt + t) * 64 + 4 * ct) =
                make_float4(o_[0], o_[1], o_[2], o_[3]);
        }
    }
}

extern "C" void kernel_launch(void* const* d_in, const int* in_sizes, int n_in,
                              void* d_out, int out_size) {
    const float* kv      = (const float*)d_in[0];
    const float* query   = (const float*)d_in[1];
    const float* keyW    = (const float*)d_in[2];
    const float* keyb    = (const float*)d_in[3];
    const float* valW    = (const float*)d_in[4];
    const float* valb    = (const float*)d_in[5];
    const float* TW      = (const float*)d_in[6];
    const float* Tb      = (const float*)d_in[7];
    const float* d1W     = (const float*)d_in[8];
    const float* d1b     = (const float*)d_in[9];
    const float* d2W     = (const float*)d_in[10];
    const float* d2b     = (const float*)d_in[11];
    const float* d3W     = (const float*)d_in[12];
    const float* d3b     = (const float*)d_in[13];
    const float* scale   = (const float*)d_in[14];
    float* out           = (float*)d_out;

    cudaFuncSetAttribute(fused_kernel, cudaFuncAttributeMaxDynamicSharedMemorySize, SMEM_BYTES);

    prep_kernel<<<160, 256>>>(keyW, valW, TW, Tb);
    fused_kernel<<<GRID, THREADS, SMEM_BYTES>>>(kv, query, keyb, valb,
                                                d1W, d1b, d2W, d2b, d3W, d3b,
                                                scale, out);
}